// round 1
// baseline (speedup 1.0000x reference)
#include <cuda_runtime.h>
#include <math.h>

#define N_PTS   32768
#define K_EMB   8192
#define DIM     32
#define KSPLIT  4
#define K_PER_SPLIT (K_EMB / KSPLIT)   // 2048
#define KT      256                     // codes per smem tile
#define THREADS 256
#define NBLK    (N_PTS / THREADS)       // 128

// ---- scratch (device globals; no allocation allowed) ----
__device__ float g_ew[K_EMB * DIM];          // normalized embedding
__device__ float g_bestval[KSPLIT * N_PTS];
__device__ int   g_bestidx[KSPLIT * N_PTS];
__device__ int   g_hist[K_EMB];
__device__ float g_part[NBLK];               // per-block sums of (2 - 2*dot)

// ---- packed f32x2 helpers (ptxas will not auto-fuse; must be PTX) ----
__device__ __forceinline__ void fma2(unsigned long long& d,
                                     unsigned long long a,
                                     unsigned long long b,
                                     unsigned long long c) {
    asm("fma.rn.f32x2 %0, %1, %2, %3;" : "=l"(d) : "l"(a), "l"(b), "l"(c));
}
__device__ __forceinline__ void add2(unsigned long long& d,
                                     unsigned long long a,
                                     unsigned long long b) {
    asm("add.rn.f32x2 %0, %1, %2;" : "=l"(d) : "l"(a), "l"(b));
}
__device__ __forceinline__ unsigned long long pack2(float lo, float hi) {
    unsigned long long u;
    asm("mov.b64 %0, {%1, %2};" : "=l"(u) : "f"(lo), "f"(hi));
    return u;
}
__device__ __forceinline__ void unpack2(unsigned long long u, float& lo, float& hi) {
    asm("mov.b64 {%0, %1}, %2;" : "=f"(lo), "=f"(hi) : "l"(u));
}

// ============================================================
// Kernel 1: normalize embedding rows, zero histogram
// grid: 32 x 256  (one thread per code row)
// ============================================================
__global__ void prep_kernel(const float* __restrict__ emb) {
    int r = blockIdx.x * blockDim.x + threadIdx.x;   // 0..8191
    g_hist[r] = 0;

    const float4* src = reinterpret_cast<const float4*>(emb + r * DIM);
    float4 v[8];
    float s = 0.f;
#pragma unroll
    for (int i = 0; i < 8; i++) {
        v[i] = src[i];
        s += v[i].x * v[i].x + v[i].y * v[i].y + v[i].z * v[i].z + v[i].w * v[i].w;
    }
    float inv = 1.0f / fmaxf(sqrtf(s), 1e-12f);
    float4* dst = reinterpret_cast<float4*>(g_ew + r * DIM);
#pragma unroll
    for (int i = 0; i < 8; i++) {
        float4 o;
        o.x = v[i].x * inv; o.y = v[i].y * inv;
        o.z = v[i].z * inv; o.w = v[i].w * inv;
        dst[i] = o;
    }
}

// ============================================================
// Kernel 2: argmax of dot(zn, ew[k]) over a K-split
// grid: (NBLK, KSPLIT) x THREADS, 1 point per thread
// ============================================================
__global__ void __launch_bounds__(THREADS)
argmax_kernel(const float* __restrict__ z) {
    __shared__ float4 tile[KT * (DIM / 4)];   // 256 rows * 32 floats = 32 KB

    const int n  = blockIdx.x * THREADS + threadIdx.x;
    const int b  = n >> 10;
    const int hw = n & 1023;

    // load this point's channel vector (stride H*W=1024 floats), normalize
    const float* zp = z + b * (DIM * 1024) + hw;
    float zn[DIM];
    float s = 0.f;
#pragma unroll
    for (int d = 0; d < DIM; d++) {
        float v = zp[d * 1024];
        zn[d] = v;
        s += v * v;
    }
    float inv = 1.0f / fmaxf(sqrtf(s), 1e-12f);
    unsigned long long z2[DIM / 2];
#pragma unroll
    for (int i = 0; i < DIM / 2; i++)
        z2[i] = pack2(zn[2 * i] * inv, zn[2 * i + 1] * inv);

    const int k0 = blockIdx.y * K_PER_SPLIT;
    float best = -2.0f;
    int   bi   = k0;

    for (int t = 0; t < K_PER_SPLIT; t += KT) {
        __syncthreads();
        const float4* src = reinterpret_cast<const float4*>(g_ew + (k0 + t) * DIM);
#pragma unroll
        for (int i = 0; i < (KT * (DIM / 4)) / THREADS; i++)
            tile[threadIdx.x + i * THREADS] = src[threadIdx.x + i * THREADS];
        __syncthreads();

#pragma unroll 2
        for (int kk = 0; kk < KT; kk++) {
            const ulonglong2* row =
                reinterpret_cast<const ulonglong2*>(&tile[kk * (DIM / 4)]);
            unsigned long long a0 = 0ull, a1 = 0ull;
#pragma unroll
            for (int i = 0; i < 8; i++) {
                ulonglong2 e = row[i];          // LDS.128, warp-broadcast
                fma2(a0, z2[2 * i],     e.x, a0);
                fma2(a1, z2[2 * i + 1], e.y, a1);
            }
            unsigned long long ss;
            add2(ss, a0, a1);
            float lo, hi;
            unpack2(ss, lo, hi);
            float dot = lo + hi;
            if (dot > best) { best = dot; bi = k0 + t + kk; }  // strict > => first max (min index)
        }
    }
    g_bestval[blockIdx.y * N_PTS + n] = best;
    g_bestidx[blockIdx.y * N_PTS + n] = bi;
}

// ============================================================
// Kernel 3: combine splits, emit idx + z_q (bchw), histogram, loss partials
// grid: NBLK x THREADS
// ============================================================
__global__ void __launch_bounds__(THREADS)
finalize_kernel(float* __restrict__ out) {
    const int n = blockIdx.x * THREADS + threadIdx.x;

    float best = g_bestval[n];
    int   bi   = g_bestidx[n];
#pragma unroll
    for (int sp = 1; sp < KSPLIT; sp++) {
        float v = g_bestval[sp * N_PTS + n];
        int   id = g_bestidx[sp * N_PTS + n];
        if (v > best) { best = v; bi = id; }   // ties keep lower split (lower k)
    }

    // idx output (as float) after z_q, loss, entropy
    out[N_PTS * DIM + 2 + n] = (float)bi;

    atomicAdd(&g_hist[bi], 1);

    // z_q gather, transposed store back to bchw
    const float4* ep = reinterpret_cast<const float4*>(g_ew + bi * DIM);
    const int b  = n >> 10;
    const int hw = n & 1023;
    float* op = out + b * (DIM * 1024) + hw;
#pragma unroll
    for (int i = 0; i < 8; i++) {
        float4 e = ep[i];
        op[(4 * i + 0) * 1024] = e.x;
        op[(4 * i + 1) * 1024] = e.y;
        op[(4 * i + 2) * 1024] = e.z;
        op[(4 * i + 3) * 1024] = e.w;
    }

    // per-block deterministic reduce of (2 - 2*dot)
    __shared__ float red[THREADS];
    red[threadIdx.x] = 2.0f - 2.0f * best;
    __syncthreads();
#pragma unroll
    for (int st = THREADS / 2; st > 0; st >>= 1) {
        if (threadIdx.x < st) red[threadIdx.x] += red[threadIdx.x + st];
        __syncthreads();
    }
    if (threadIdx.x == 0) g_part[blockIdx.x] = red[0];
}

// ============================================================
// Kernel 4: entropy + loss scalars
// grid: 1 x 256
// ============================================================
__global__ void scalars_kernel(float* __restrict__ out) {
    const int t = threadIdx.x;
    __shared__ float sh[THREADS];

    // entropy over all 8192 bins (zero-count bins included via +eps)
    const float denom = (float)N_PTS + (float)K_EMB * 1e-4f;
    const float invd  = 1.0f / denom;
    float acc = 0.f;
#pragma unroll
    for (int i = 0; i < K_EMB / THREADS; i++) {
        float p = ((float)g_hist[t * (K_EMB / THREADS) + i] + 1e-4f) * invd;
        acc += p * logf(p);
    }
    sh[t] = acc;
    __syncthreads();
#pragma unroll
    for (int st = THREADS / 2; st > 0; st >>= 1) {
        if (t < st) sh[t] += sh[t + st];
        __syncthreads();
    }
    float entropy = -sh[0];
    __syncthreads();

    // loss = 1.25 * mean(2 - 2*dot)
    sh[t] = (t < NBLK) ? g_part[t] : 0.f;
    __syncthreads();
#pragma unroll
    for (int st = THREADS / 2; st > 0; st >>= 1) {
        if (t < st) sh[t] += sh[t + st];
        __syncthreads();
    }
    if (t == 0) {
        out[N_PTS * DIM + 0] = 1.25f * (sh[0] / (float)N_PTS);
        out[N_PTS * DIM + 1] = entropy;
    }
}

// ============================================================
extern "C" void kernel_launch(void* const* d_in, const int* in_sizes, int n_in,
                              void* d_out, int out_size) {
    const float* z   = (const float*)d_in[0];
    const float* emb = (const float*)d_in[1];
    if (n_in >= 2 && in_sizes[0] == K_EMB * DIM && in_sizes[1] == N_PTS * DIM) {
        // defensive: inputs arrived swapped
        z   = (const float*)d_in[1];
        emb = (const float*)d_in[0];
    }
    float* out = (float*)d_out;

    prep_kernel<<<K_EMB / THREADS, THREADS>>>(emb);
    argmax_kernel<<<dim3(NBLK, KSPLIT), THREADS>>>(z);
    finalize_kernel<<<NBLK, THREADS>>>(out);
    scalars_kernel<<<1, THREADS>>>(out);
}

// round 2
// speedup vs baseline: 1.4647x; 1.4647x over previous
#include <cuda_runtime.h>
#include <math.h>

#define N_PTS   32768
#define K_EMB   8192
#define DIM     32
#define KSPLIT  16
#define K_PER_SPLIT (K_EMB / KSPLIT)    // 512
#define KT      256                      // codes per smem tile
#define THREADS 256
#define GRID_ARG 148
#define CHUNKS  (N_PTS / (THREADS * 2))  // 64 (2 points per thread)
#define ITEMS   (CHUNKS * KSPLIT)        // 1024
#define NBLK    (N_PTS / THREADS)        // 128

// ---- scratch (device globals; no allocation allowed) ----
__device__ float g_ew[K_EMB * DIM];          // normalized embedding
__device__ float g_bestval[KSPLIT * N_PTS];
__device__ int   g_bestidx[KSPLIT * N_PTS];
__device__ int   g_hist[K_EMB];
__device__ float g_part[NBLK];               // per-block sums of (2 - 2*dot)
__device__ float g_entp[32];                 // entropy partials

// ---- packed f32x2 helpers ----
__device__ __forceinline__ void fma2(unsigned long long& d,
                                     unsigned long long a,
                                     unsigned long long b,
                                     unsigned long long c) {
    asm("fma.rn.f32x2 %0, %1, %2, %3;" : "=l"(d) : "l"(a), "l"(b), "l"(c));
}
__device__ __forceinline__ void mul2(unsigned long long& d,
                                     unsigned long long a,
                                     unsigned long long b) {
    asm("mul.rn.f32x2 %0, %1, %2;" : "=l"(d) : "l"(a), "l"(b));
}
__device__ __forceinline__ void add2(unsigned long long& d,
                                     unsigned long long a,
                                     unsigned long long b) {
    asm("add.rn.f32x2 %0, %1, %2;" : "=l"(d) : "l"(a), "l"(b));
}
__device__ __forceinline__ unsigned long long pack2(float lo, float hi) {
    unsigned long long u;
    asm("mov.b64 %0, {%1, %2};" : "=l"(u) : "f"(lo), "f"(hi));
    return u;
}
__device__ __forceinline__ void unpack2(unsigned long long u, float& lo, float& hi) {
    asm("mov.b64 {%0, %1}, %2;" : "=f"(lo), "=f"(hi) : "l"(u));
}

// ============================================================
// Kernel 1: normalize embedding rows, zero histogram
// (source identical to round 1 -> bit-identical g_ew)
// ============================================================
__global__ void prep_kernel(const float* __restrict__ emb) {
    int r = blockIdx.x * blockDim.x + threadIdx.x;   // 0..8191
    g_hist[r] = 0;

    const float4* src = reinterpret_cast<const float4*>(emb + r * DIM);
    float4 v[8];
    float s = 0.f;
#pragma unroll
    for (int i = 0; i < 8; i++) {
        v[i] = src[i];
        s += v[i].x * v[i].x + v[i].y * v[i].y + v[i].z * v[i].z + v[i].w * v[i].w;
    }
    float inv = 1.0f / fmaxf(sqrtf(s), 1e-12f);
    float4* dst = reinterpret_cast<float4*>(g_ew + r * DIM);
#pragma unroll
    for (int i = 0; i < 8; i++) {
        float4 o;
        o.x = v[i].x * inv; o.y = v[i].y * inv;
        o.z = v[i].z * inv; o.w = v[i].w * inv;
        dst[i] = o;
    }
}

// load one point's channel vector, normalize exactly as round 1,
// emit duplicated packed (z_d, z_d) pairs
__device__ __forceinline__ void load_point_dup(const float* __restrict__ z,
                                               int n, unsigned long long* zd) {
    const int b  = n >> 10;
    const int hw = n & 1023;
    const float* zp = z + b * (DIM * 1024) + hw;
    float zn[DIM];
    float s = 0.f;
#pragma unroll
    for (int d = 0; d < DIM; d++) {
        float v = zp[d * 1024];
        zn[d] = v;
        s += v * v;
    }
    float inv = 1.0f / fmaxf(sqrtf(s), 1e-12f);
#pragma unroll
    for (int d = 0; d < DIM; d++) {
        float t = zn[d] * inv;
        zd[d] = pack2(t, t);
    }
}

// ============================================================
// Kernel 2: persistent argmax sweep
// grid: 148 x 256, items = (point-chunk, k-split)
// smem tile transposed [d][k]; 4 code rows per f32x2 group;
// 2 points per thread
// ============================================================
__global__ void __launch_bounds__(THREADS, 1)
argmax_kernel(const float* __restrict__ z) {
    __shared__ float tile[DIM * KT];   // [d][k], 32 KB

    for (int it = blockIdx.x; it < ITEMS; it += GRID_ARG) {
        const int chunk = it >> 4;        // 0..63
        const int sp    = it & (KSPLIT - 1);
        const int n0    = chunk * (THREADS * 2);
        const int n_a   = n0 + threadIdx.x;
        const int n_b   = n_a + THREADS;

        unsigned long long za[DIM], zb[DIM];
        load_point_dup(z, n_a, za);
        load_point_dup(z, n_b, zb);

        float best_a = -2.0f, best_b = -2.0f;
        int   bi_a = sp * K_PER_SPLIT, bi_b = sp * K_PER_SPLIT;

        for (int t = 0; t < K_PER_SPLIT; t += KT) {
            const int kbase = sp * K_PER_SPLIT + t;
            __syncthreads();
            // build transposed tile: each thread loads one code row
            {
                const float4* src =
                    reinterpret_cast<const float4*>(g_ew + (kbase + threadIdx.x) * DIM);
#pragma unroll
                for (int i = 0; i < 8; i++) {
                    float4 v = src[i];
                    tile[(4 * i + 0) * KT + threadIdx.x] = v.x;
                    tile[(4 * i + 1) * KT + threadIdx.x] = v.y;
                    tile[(4 * i + 2) * KT + threadIdx.x] = v.z;
                    tile[(4 * i + 3) * KT + threadIdx.x] = v.w;
                }
            }
            __syncthreads();

#pragma unroll 1
            for (int g = 0; g < KT; g += 4) {
                // 4 chains per (point, row-pair), split by d mod 4,
                // combined (S0+S2)+(S1+S3): bit-identical to round-1 dots
                unsigned long long a01[4], a23[4], b01[4], b23[4];
#pragma unroll
                for (int d = 0; d < DIM; d++) {
                    ulonglong2 e =
                        *reinterpret_cast<const ulonglong2*>(tile + d * KT + g);
                    if (d < 4) {
                        mul2(a01[d], za[d], e.x);
                        mul2(a23[d], za[d], e.y);
                        mul2(b01[d], zb[d], e.x);
                        mul2(b23[d], zb[d], e.y);
                    } else {
                        fma2(a01[d & 3], za[d], e.x, a01[d & 3]);
                        fma2(a23[d & 3], za[d], e.y, a23[d & 3]);
                        fma2(b01[d & 3], zb[d], e.x, b01[d & 3]);
                        fma2(b23[d & 3], zb[d], e.y, b23[d & 3]);
                    }
                }
                unsigned long long u, v, s01, s23;
                float d0, d1, d2, d3;
                const int kk = kbase + g;

                add2(u, a01[0], a01[2]); add2(v, a01[1], a01[3]); add2(s01, u, v);
                add2(u, a23[0], a23[2]); add2(v, a23[1], a23[3]); add2(s23, u, v);
                unpack2(s01, d0, d1); unpack2(s23, d2, d3);
                if (d0 > best_a) { best_a = d0; bi_a = kk; }
                if (d1 > best_a) { best_a = d1; bi_a = kk + 1; }
                if (d2 > best_a) { best_a = d2; bi_a = kk + 2; }
                if (d3 > best_a) { best_a = d3; bi_a = kk + 3; }

                add2(u, b01[0], b01[2]); add2(v, b01[1], b01[3]); add2(s01, u, v);
                add2(u, b23[0], b23[2]); add2(v, b23[1], b23[3]); add2(s23, u, v);
                unpack2(s01, d0, d1); unpack2(s23, d2, d3);
                if (d0 > best_b) { best_b = d0; bi_b = kk; }
                if (d1 > best_b) { best_b = d1; bi_b = kk + 1; }
                if (d2 > best_b) { best_b = d2; bi_b = kk + 2; }
                if (d3 > best_b) { best_b = d3; bi_b = kk + 3; }
            }
        }
        g_bestval[sp * N_PTS + n_a] = best_a;
        g_bestidx[sp * N_PTS + n_a] = bi_a;
        g_bestval[sp * N_PTS + n_b] = best_b;
        g_bestidx[sp * N_PTS + n_b] = bi_b;
    }
}

// ============================================================
// Kernel 3: combine splits, emit idx + z_q (bchw), histogram, loss partials
// ============================================================
__global__ void __launch_bounds__(THREADS)
finalize_kernel(float* __restrict__ out) {
    const int n = blockIdx.x * THREADS + threadIdx.x;

    float best = g_bestval[n];
    int   bi   = g_bestidx[n];
#pragma unroll
    for (int sp = 1; sp < KSPLIT; sp++) {
        float v  = g_bestval[sp * N_PTS + n];
        int   id = g_bestidx[sp * N_PTS + n];
        if (v > best) { best = v; bi = id; }   // ties keep lower split (lower k)
    }

    out[N_PTS * DIM + 2 + n] = (float)bi;
    atomicAdd(&g_hist[bi], 1);

    const float4* ep = reinterpret_cast<const float4*>(g_ew + bi * DIM);
    const int b  = n >> 10;
    const int hw = n & 1023;
    float* op = out + b * (DIM * 1024) + hw;
#pragma unroll
    for (int i = 0; i < 8; i++) {
        float4 e = ep[i];
        op[(4 * i + 0) * 1024] = e.x;
        op[(4 * i + 1) * 1024] = e.y;
        op[(4 * i + 2) * 1024] = e.z;
        op[(4 * i + 3) * 1024] = e.w;
    }

    __shared__ float red[THREADS];
    red[threadIdx.x] = 2.0f - 2.0f * best;
    __syncthreads();
#pragma unroll
    for (int st = THREADS / 2; st > 0; st >>= 1) {
        if (threadIdx.x < st) red[threadIdx.x] += red[threadIdx.x + st];
        __syncthreads();
    }
    if (threadIdx.x == 0) g_part[blockIdx.x] = red[0];
}

// ============================================================
// Kernel 4a: entropy partials (parallel logs across 32 blocks)
// ============================================================
__global__ void ent_kernel() {
    const int bin = blockIdx.x * 256 + threadIdx.x;
    const float denom = (float)N_PTS + (float)K_EMB * 1e-4f;
    const float invd  = 1.0f / denom;
    float p = ((float)g_hist[bin] + 1e-4f) * invd;
    __shared__ float sh[256];
    sh[threadIdx.x] = p * logf(p);
    __syncthreads();
#pragma unroll
    for (int st = 128; st > 0; st >>= 1) {
        if (threadIdx.x < st) sh[threadIdx.x] += sh[threadIdx.x + st];
        __syncthreads();
    }
    if (threadIdx.x == 0) g_entp[blockIdx.x] = sh[0];
}

// ============================================================
// Kernel 4b: final scalars (entropy + loss), fixed-order reductions
// ============================================================
__global__ void scalars_kernel(float* __restrict__ out) {
    const int t = threadIdx.x;
    __shared__ float sh[THREADS];

    sh[t] = (t < 32) ? g_entp[t] : 0.f;
    __syncthreads();
#pragma unroll
    for (int st = THREADS / 2; st > 0; st >>= 1) {
        if (t < st) sh[t] += sh[t + st];
        __syncthreads();
    }
    float entropy = -sh[0];
    __syncthreads();

    sh[t] = (t < NBLK) ? g_part[t] : 0.f;
    __syncthreads();
#pragma unroll
    for (int st = THREADS / 2; st > 0; st >>= 1) {
        if (t < st) sh[t] += sh[t + st];
        __syncthreads();
    }
    if (t == 0) {
        out[N_PTS * DIM + 0] = 1.25f * (sh[0] / (float)N_PTS);
        out[N_PTS * DIM + 1] = entropy;
    }
}

// ============================================================
extern "C" void kernel_launch(void* const* d_in, const int* in_sizes, int n_in,
                              void* d_out, int out_size) {
    const float* z   = (const float*)d_in[0];
    const float* emb = (const float*)d_in[1];
    if (n_in >= 2 && in_sizes[0] == K_EMB * DIM && in_sizes[1] == N_PTS * DIM) {
        z   = (const float*)d_in[1];
        emb = (const float*)d_in[0];
    }
    float* out = (float*)d_out;

    prep_kernel<<<K_EMB / THREADS, THREADS>>>(emb);
    argmax_kernel<<<GRID_ARG, THREADS>>>(z);
    finalize_kernel<<<NBLK, THREADS>>>(out);
    ent_kernel<<<32, 256>>>();
    scalars_kernel<<<1, THREADS>>>(out);
}